// round 4
// baseline (speedup 1.0000x reference)
#include <cuda_runtime.h>
#include <cuda_bf16.h>

// Problem dims (fixed by the reference)
#define BATCH 4
#define SEQ   4096
#define DMODEL 1024

// ---------------------------------------------------------------------------
// Scratch (device globals; no dynamic allocation allowed)
// ---------------------------------------------------------------------------
__device__ float g_Q[(long)BATCH * SEQ * DMODEL];   //  64 MB
__device__ float g_V[(long)BATCH * SEQ * DMODEL];   //  64 MB
__device__ float g_S[(long)BATCH * SEQ * SEQ];      // 256 MB

// ---------------------------------------------------------------------------
// GEMM NT: C[m,n] = scale * sum_k A[m,k] * B[n,k]  (+ bias1[n] + bias2[n])
// A row-major [M,K], B row-major [N,K]. BM=BN=128, BK=32, 256 thr, 8x8 tiles.
// All dims assumed multiples of the tile sizes (true for this problem).
// ---------------------------------------------------------------------------
#define BM 128
#define BN 128
#define BK 32

__global__ __launch_bounds__(256)
void gemm_nt(const float* __restrict__ A, const float* __restrict__ B,
             float* __restrict__ C,
             int M, int N, int K,
             const float* __restrict__ bias1, const float* __restrict__ bias2,
             float scale,
             long long aBatch, long long bBatch, long long cBatch)
{
    const int bz = blockIdx.z;
    A += (long long)bz * aBatch;
    B += (long long)bz * bBatch;
    C += (long long)bz * cBatch;

    __shared__ float As[BK][BM];
    __shared__ float Bs[BK][BN];

    const int m0 = blockIdx.y * BM;
    const int n0 = blockIdx.x * BN;
    const int tid = threadIdx.x;

    const int tm = (tid >> 4) << 3;   // 0..120
    const int tn = (tid & 15) << 3;   // 0..120

    float acc[8][8];
    #pragma unroll
    for (int i = 0; i < 8; i++)
        #pragma unroll
        for (int j = 0; j < 8; j++) acc[i][j] = 0.f;

    for (int k0 = 0; k0 < K; k0 += BK) {
        // load A tile (128 rows x 32 k) transposed into As[k][m]
        #pragma unroll
        for (int i = 0; i < 4; i++) {
            int idx = tid + 256 * i;      // 0..1023
            int r   = idx >> 3;           // 0..127
            int c4  = idx & 7;            // 0..7 (float4 slot)
            float4 v = *(const float4*)(A + (long long)(m0 + r) * K + k0 + c4 * 4);
            As[c4 * 4 + 0][r] = v.x;
            As[c4 * 4 + 1][r] = v.y;
            As[c4 * 4 + 2][r] = v.z;
            As[c4 * 4 + 3][r] = v.w;
        }
        // load B tile (128 rows x 32 k) transposed into Bs[k][n]
        #pragma unroll
        for (int i = 0; i < 4; i++) {
            int idx = tid + 256 * i;
            int r   = idx >> 3;
            int c4  = idx & 7;
            float4 v = *(const float4*)(B + (long long)(n0 + r) * K + k0 + c4 * 4);
            Bs[c4 * 4 + 0][r] = v.x;
            Bs[c4 * 4 + 1][r] = v.y;
            Bs[c4 * 4 + 2][r] = v.z;
            Bs[c4 * 4 + 3][r] = v.w;
        }
        __syncthreads();

        #pragma unroll
        for (int kk = 0; kk < BK; kk++) {
            float4 a0 = *(const float4*)&As[kk][tm];
            float4 a1 = *(const float4*)&As[kk][tm + 4];
            float4 b0 = *(const float4*)&Bs[kk][tn];
            float4 b1 = *(const float4*)&Bs[kk][tn + 4];
            float a[8] = {a0.x, a0.y, a0.z, a0.w, a1.x, a1.y, a1.z, a1.w};
            float b[8] = {b0.x, b0.y, b0.z, b0.w, b1.x, b1.y, b1.z, b1.w};
            #pragma unroll
            for (int i = 0; i < 8; i++)
                #pragma unroll
                for (int j = 0; j < 8; j++)
                    acc[i][j] = fmaf(a[i], b[j], acc[i][j]);
        }
        __syncthreads();
    }

    #pragma unroll
    for (int i = 0; i < 8; i++) {
        const long long m = m0 + tm + i;
        #pragma unroll
        for (int j = 0; j < 8; j++) {
            const int n = n0 + tn + j;
            float v = acc[i][j] * scale;
            if (bias1) v += bias1[n];
            if (bias2) v += bias2[n];
            C[m * N + n] = v;
        }
    }
}

// ---------------------------------------------------------------------------
// GEMM NN: C[m,n] = sum_k A[m,k] * B[k,n]
// A row-major [M,K], B row-major [K,N].
// ---------------------------------------------------------------------------
__global__ __launch_bounds__(256)
void gemm_nn(const float* __restrict__ A, const float* __restrict__ B,
             float* __restrict__ C,
             int M, int N, int K,
             long long aBatch, long long bBatch, long long cBatch)
{
    const int bz = blockIdx.z;
    A += (long long)bz * aBatch;
    B += (long long)bz * bBatch;
    C += (long long)bz * cBatch;

    __shared__ float As[BK][BM];
    __shared__ float Bs[BK][BN];

    const int m0 = blockIdx.y * BM;
    const int n0 = blockIdx.x * BN;
    const int tid = threadIdx.x;

    const int tm = (tid >> 4) << 3;
    const int tn = (tid & 15) << 3;

    float acc[8][8];
    #pragma unroll
    for (int i = 0; i < 8; i++)
        #pragma unroll
        for (int j = 0; j < 8; j++) acc[i][j] = 0.f;

    for (int k0 = 0; k0 < K; k0 += BK) {
        // A tile transposed (same as NT)
        #pragma unroll
        for (int i = 0; i < 4; i++) {
            int idx = tid + 256 * i;
            int r   = idx >> 3;
            int c4  = idx & 7;
            float4 v = *(const float4*)(A + (long long)(m0 + r) * K + k0 + c4 * 4);
            As[c4 * 4 + 0][r] = v.x;
            As[c4 * 4 + 1][r] = v.y;
            As[c4 * 4 + 2][r] = v.z;
            As[c4 * 4 + 3][r] = v.w;
        }
        // B tile: rows k0..k0+31, cols n0..n0+127 (natural layout)
        #pragma unroll
        for (int i = 0; i < 4; i++) {
            int idx = tid + 256 * i;      // 0..1023
            int r   = idx >> 5;           // 0..31 (k within tile)
            int c4  = idx & 31;           // 0..31 (float4 along n)
            float4 v = *(const float4*)(B + (long long)(k0 + r) * N + n0 + c4 * 4);
            *(float4*)&Bs[r][c4 * 4] = v;
        }
        __syncthreads();

        #pragma unroll
        for (int kk = 0; kk < BK; kk++) {
            float4 a0 = *(const float4*)&As[kk][tm];
            float4 a1 = *(const float4*)&As[kk][tm + 4];
            float4 b0 = *(const float4*)&Bs[kk][tn];
            float4 b1 = *(const float4*)&Bs[kk][tn + 4];
            float a[8] = {a0.x, a0.y, a0.z, a0.w, a1.x, a1.y, a1.z, a1.w};
            float b[8] = {b0.x, b0.y, b0.z, b0.w, b1.x, b1.y, b1.z, b1.w};
            #pragma unroll
            for (int i = 0; i < 8; i++)
                #pragma unroll
                for (int j = 0; j < 8; j++)
                    acc[i][j] = fmaf(a[i], b[j], acc[i][j]);
        }
        __syncthreads();
    }

    #pragma unroll
    for (int i = 0; i < 8; i++) {
        const long long m = m0 + tm + i;
        #pragma unroll
        for (int j = 0; j < 8; j++) {
            C[m * N + n0 + tn + j] = acc[i][j];
        }
    }
}

// ---------------------------------------------------------------------------
// Row softmax in place. One block (512 threads) per row of length 4096.
// Row data stays in registers (two float4 per thread).
// ---------------------------------------------------------------------------
__global__ __launch_bounds__(512)
void softmax_rows(float* __restrict__ S)
{
    const int n = SEQ;                                // 4096
    float* p = S + (long long)blockIdx.x * n;
    const int tid = threadIdx.x;                      // 0..511

    float4 a = ((const float4*)p)[tid];
    float4 b = ((const float4*)p)[tid + 512];

    __shared__ float sred[16];
    __shared__ float sval;

    // ---- max ----
    float m = fmaxf(fmaxf(fmaxf(a.x, a.y), fmaxf(a.z, a.w)),
                    fmaxf(fmaxf(b.x, b.y), fmaxf(b.z, b.w)));
    #pragma unroll
    for (int o = 16; o > 0; o >>= 1)
        m = fmaxf(m, __shfl_xor_sync(0xffffffffu, m, o));
    if ((tid & 31) == 0) sred[tid >> 5] = m;
    __syncthreads();
    if (tid < 32) {
        float x = (tid < 16) ? sred[tid] : __int_as_float(0xff800000);
        #pragma unroll
        for (int o = 8; o > 0; o >>= 1)
            x = fmaxf(x, __shfl_xor_sync(0xffffffffu, x, o));
        if (tid == 0) sval = x;
    }
    __syncthreads();
    const float rmax = sval;
    __syncthreads();

    // ---- exp + sum ----
    a.x = expf(a.x - rmax); a.y = expf(a.y - rmax);
    a.z = expf(a.z - rmax); a.w = expf(a.w - rmax);
    b.x = expf(b.x - rmax); b.y = expf(b.y - rmax);
    b.z = expf(b.z - rmax); b.w = expf(b.w - rmax);

    float s = (a.x + a.y) + (a.z + a.w) + (b.x + b.y) + (b.z + b.w);
    #pragma unroll
    for (int o = 16; o > 0; o >>= 1)
        s += __shfl_xor_sync(0xffffffffu, s, o);
    if ((tid & 31) == 0) sred[tid >> 5] = s;
    __syncthreads();
    if (tid < 32) {
        float x = (tid < 16) ? sred[tid] : 0.f;
        #pragma unroll
        for (int o = 8; o > 0; o >>= 1)
            x += __shfl_xor_sync(0xffffffffu, x, o);
        if (tid == 0) sval = x;
    }
    __syncthreads();
    const float inv = 1.0f / sval;

    a.x *= inv; a.y *= inv; a.z *= inv; a.w *= inv;
    b.x *= inv; b.y *= inv; b.z *= inv; b.w *= inv;
    ((float4*)p)[tid]       = a;
    ((float4*)p)[tid + 512] = b;
}

// ---------------------------------------------------------------------------
// Launcher
// ---------------------------------------------------------------------------
extern "C" void kernel_launch(void* const* d_in, const int* in_sizes, int n_in,
                              void* d_out, int out_size)
{
    const float* query = (const float*)d_in[0];
    const float* value = (const float*)d_in[1];
    const float* Wq    = (const float*)d_in[2];
    const float* bq    = (const float*)d_in[3];
    const float* qkb   = (const float*)d_in[4];
    const float* Wv    = (const float*)d_in[5];
    const float* bv    = (const float*)d_in[6];
    float* out = (float*)d_out;

    float *pQ, *pV, *pS;
    cudaGetSymbolAddress((void**)&pQ, g_Q);
    cudaGetSymbolAddress((void**)&pV, g_V);
    cudaGetSymbolAddress((void**)&pS, g_S);

    const int B = BATCH, S = SEQ, D = DMODEL;

    // 1) projections: Q = query·Wq^T + bq + qk_b ; V = value·Wv^T + bv
    dim3 gp(D / BN, (B * S) / BM, 1);
    gemm_nt<<<gp, 256>>>(query, Wq, pQ, B * S, D, D, bq, qkb, 1.0f, 0, 0, 0);
    gemm_nt<<<gp, 256>>>(value, Wv, pV, B * S, D, D, bv, nullptr, 1.0f, 0, 0, 0);

    // 2) scores: S[b] = Q[b]·V[b]^T / 8
    dim3 gs(S / BN, S / BM, B);
    gemm_nt<<<gs, 256>>>(pQ, pV, pS, S, S, D, nullptr, nullptr, 0.125f,
                         (long long)S * D, (long long)S * D, (long long)S * S);

    // 3) softmax over last axis, in place
    softmax_rows<<<B * S, 512>>>(pS);

    // 4) out[b] = P[b]·V[b]
    dim3 go(D / BN, S / BM, B);
    gemm_nn<<<go, 256>>>(pS, pV, out, S, D, S,
                         (long long)S * S, (long long)S * D, (long long)S * D);
}

// round 6
// speedup vs baseline: 2.5613x; 2.5613x over previous
#include <cuda_runtime.h>
#include <cuda_bf16.h>
#include <cstdint>

#define BATCH  4
#define SEQ    4096
#define DMODEL 1024

// GEMM tiles: CTA 128x128, 512 threads (16 warps, 4x4), warp tile 32x32.
// K processed in chunks of 32 fp32; each chunk split to bf16 hi/lo in smem.
#define BM 128
#define BN 128
#define BK 32
#define THREADS 512

// smem per stage: A_hi, A_lo, B_hi, B_lo; each 128 rows x 80 bytes (32 bf16 + pad)
#define ROW_B   80
#define HALF_B  (128 * ROW_B)          // 10240
#define STAGE_B (4 * HALF_B)           // 40960
#define SMEM_DYN (2 * STAGE_B)         // 81920

// ---------------------------------------------------------------------------
// Scratch (device globals; allocation is forbidden)
// ---------------------------------------------------------------------------
__device__ float g_Q [(size_t)BATCH * SEQ * DMODEL];   //  64 MB
__device__ float g_V [(size_t)BATCH * SEQ * DMODEL];   //  64 MB
__device__ float g_Vt[(size_t)BATCH * SEQ * DMODEL];   //  64 MB
__device__ float g_S [(size_t)BATCH * SEQ * SEQ];      // 256 MB

// ---------------------------------------------------------------------------
// helpers
// ---------------------------------------------------------------------------
__device__ __forceinline__ uint32_t smem_u32(const void* p) {
    uint32_t a;
    asm("{ .reg .u64 t; cvta.to.shared.u64 t, %1; cvt.u32.u64 %0, t; }" : "=r"(a) : "l"(p));
    return a;
}

#define LDSM4(d, addr) \
    asm volatile("ldmatrix.sync.aligned.m8n8.x4.shared.b16 {%0,%1,%2,%3}, [%4];" \
        : "=r"((d)[0]), "=r"((d)[1]), "=r"((d)[2]), "=r"((d)[3]) : "r"(addr))

#define MMA_BF16(d, a, b) \
    asm volatile("mma.sync.aligned.m16n8k16.row.col.f32.bf16.bf16.f32 " \
        "{%0,%1,%2,%3}, {%4,%5,%6,%7}, {%8,%9}, {%0,%1,%2,%3};" \
        : "+f"((d)[0]), "+f"((d)[1]), "+f"((d)[2]), "+f"((d)[3]) \
        : "r"((a)[0]), "r"((a)[1]), "r"((a)[2]), "r"((a)[3]), \
          "r"((b)[0]), "r"((b)[1]))

// split 8 fp32 -> 8 bf16 hi (uint4) + 8 bf16 lo (uint4)
__device__ __forceinline__ void split8(const float4& x, const float4& y,
                                       uint4& hi, uint4& lo)
{
    float f[8] = {x.x, x.y, x.z, x.w, y.x, y.y, y.z, y.w};
    uint32_t h[4], l[4];
    #pragma unroll
    for (int i = 0; i < 4; ++i) {
        __nv_bfloat16 h0 = __float2bfloat16(f[2 * i]);
        __nv_bfloat16 h1 = __float2bfloat16(f[2 * i + 1]);
        float r0 = f[2 * i]     - __bfloat162float(h0);
        float r1 = f[2 * i + 1] - __bfloat162float(h1);
        __nv_bfloat162 hp = __nv_bfloat162(h0, h1);
        __nv_bfloat162 lp = __floats2bfloat162_rn(r0, r1);
        h[i] = *reinterpret_cast<uint32_t*>(&hp);
        l[i] = *reinterpret_cast<uint32_t*>(&lp);
    }
    hi = make_uint4(h[0], h[1], h[2], h[3]);
    lo = make_uint4(l[0], l[1], l[2], l[3]);
}

// ---------------------------------------------------------------------------
// bf16 3-term-split NT GEMM:
//   C[m,n] = scale * sum_k A[m,k]*B[n,k] (+ b1[n] + b2[n])
// A row-major [M,K] lda, B row-major [N,K] ldb. fp32 accumulate via mma.sync.
// ---------------------------------------------------------------------------
__global__ __launch_bounds__(THREADS, 1)
void gemm_nt_mma(const float* __restrict__ A, const float* __restrict__ B,
                 float* __restrict__ C,
                 int K, int lda, int ldb, int ldc,
                 const float* __restrict__ b1, const float* __restrict__ b2,
                 float scale,
                 long long aB, long long bB, long long cB)
{
    extern __shared__ char smem[];
    const uint32_t sbase = smem_u32(smem);

    const int tid  = threadIdx.x;
    const int lane = tid & 31;
    const int w    = tid >> 5;      // 0..15
    const int wm   = w & 3;         // m 32-block
    const int wn   = w >> 2;        // n 32-block

    A += (long long)blockIdx.z * aB;
    B += (long long)blockIdx.z * bB;
    C += (long long)blockIdx.z * cB;
    const int m0 = blockIdx.y * BM;
    const int n0 = blockIdx.x * BN;

    // per-thread ldmatrix byte offsets within a 128x80B half-tile
    // A x4 (m16 x k16): matrix j=lane>>3: row += 8 if (j&1); k += 8 if (j>>1)
    uint32_t offA[2], offB[2];
    #pragma unroll
    for (int t = 0; t < 2; ++t) {
        int rA = wm * 32 + t * 16 + ((lane >> 3) & 1) * 8 + (lane & 7);
        offA[t] = (uint32_t)(rA * ROW_B + ((lane >> 4) & 1) * 16);
        int rB = wn * 32 + t * 16 + ((lane >> 4) & 1) * 8 + (lane & 7);
        offB[t] = (uint32_t)(rB * ROW_B + ((lane >> 3) & 1) * 16);
    }

    // gmem load / smem store mapping: each thread: row r, 8-k chunk c8
    const int r  = tid >> 2;        // 0..127
    const int c8 = tid & 3;         // 0..3
    const uint32_t st_off = (uint32_t)(r * ROW_B + c8 * 16);

    const float* Ag = A + (long long)(m0 + r) * lda + c8 * 8;
    const float* Bg = B + (long long)(n0 + r) * ldb + c8 * 8;

    float acc[2][4][4];
    #pragma unroll
    for (int i = 0; i < 2; ++i)
        #pragma unroll
        for (int j = 0; j < 4; ++j)
            #pragma unroll
            for (int q = 0; q < 4; ++q) acc[i][j][q] = 0.f;

    const int nc = K >> 5;

    // prologue: chunk 0
    float4 va0 = *(const float4*)(Ag);
    float4 va1 = *(const float4*)(Ag + 4);
    float4 vb0 = *(const float4*)(Bg);
    float4 vb1 = *(const float4*)(Bg + 4);
    {
        uint4 hi, lo;
        split8(va0, va1, hi, lo);
        *(uint4*)(smem + st_off)          = hi;
        *(uint4*)(smem + HALF_B + st_off) = lo;
        split8(vb0, vb1, hi, lo);
        *(uint4*)(smem + 2 * HALF_B + st_off) = hi;
        *(uint4*)(smem + 3 * HALF_B + st_off) = lo;
    }
    __syncthreads();

    for (int c = 0; c < nc; ++c) {
        // prefetch next chunk to regs (overlaps with MMA below)
        if (c + 1 < nc) {
            const float* An = Ag + (c + 1) * 32;
            const float* Bn = Bg + (c + 1) * 32;
            va0 = *(const float4*)(An);
            va1 = *(const float4*)(An + 4);
            vb0 = *(const float4*)(Bn);
            vb1 = *(const float4*)(Bn + 4);
        }

        // compute on buffer c&1
        const uint32_t base = sbase + (uint32_t)(c & 1) * STAGE_B;
        #pragma unroll
        for (int kk2 = 0; kk2 < 2; ++kk2) {
            const uint32_t kb = kk2 * 32;    // 16 bf16 = 32 bytes
            uint32_t ah[2][4], al[2][4], bh[2][4], bl[2][4];
            #pragma unroll
            for (int t = 0; t < 2; ++t) {
                LDSM4(ah[t], base + offA[t] + kb);
                LDSM4(al[t], base + HALF_B + offA[t] + kb);
                LDSM4(bh[t], base + 2 * HALF_B + offB[t] + kb);
                LDSM4(bl[t], base + 3 * HALF_B + offB[t] + kb);
            }
            #pragma unroll
            for (int mi = 0; mi < 2; ++mi)
                #pragma unroll
                for (int nt = 0; nt < 2; ++nt)
                    #pragma unroll
                    for (int nh = 0; nh < 2; ++nh) {
                        const int ni = nt * 2 + nh;
                        uint32_t bhf[2] = {bh[nt][nh * 2], bh[nt][nh * 2 + 1]};
                        uint32_t blf[2] = {bl[nt][nh * 2], bl[nt][nh * 2 + 1]};
                        MMA_BF16(acc[mi][ni], ah[mi], bhf);
                        MMA_BF16(acc[mi][ni], ah[mi], blf);
                        MMA_BF16(acc[mi][ni], al[mi], bhf);
                    }
        }
        __syncthreads();

        if (c + 1 < nc) {
            char* stp = smem + ((c + 1) & 1) * STAGE_B;
            uint4 hi, lo;
            split8(va0, va1, hi, lo);
            *(uint4*)(stp + st_off)          = hi;
            *(uint4*)(stp + HALF_B + st_off) = lo;
            split8(vb0, vb1, hi, lo);
            *(uint4*)(stp + 2 * HALF_B + st_off) = hi;
            *(uint4*)(stp + 3 * HALF_B + st_off) = lo;
            __syncthreads();
        }
    }

    // epilogue: thread owns rows gid, gid+8; cols tig*2,+1 per mma tile
    const int gid = lane >> 2;
    const int tig = lane & 3;
    #pragma unroll
    for (int mi = 0; mi < 2; ++mi) {
        const int row = m0 + wm * 32 + mi * 16 + gid;
        #pragma unroll
        for (int ni = 0; ni < 4; ++ni) {
            const int col = n0 + wn * 32 + ni * 8 + tig * 2;
            float bb0 = 0.f, bb1 = 0.f;
            if (b1) { bb0 += b1[col]; bb1 += b1[col + 1]; }
            if (b2) { bb0 += b2[col]; bb1 += b2[col + 1]; }
            float2 o0, o1;
            o0.x = acc[mi][ni][0] * scale + bb0;
            o0.y = acc[mi][ni][1] * scale + bb1;
            o1.x = acc[mi][ni][2] * scale + bb0;
            o1.y = acc[mi][ni][3] * scale + bb1;
            *(float2*)(C + (long long)row * ldc + col)       = o0;
            *(float2*)(C + (long long)(row + 8) * ldc + col) = o1;
        }
    }
}

// ---------------------------------------------------------------------------
// V transpose: Vt[b][d][s] = V[b][s][d]
// ---------------------------------------------------------------------------
__global__ __launch_bounds__(256)
void transpose_v(const float* __restrict__ V, float* __restrict__ Vt)
{
    __shared__ float t[32][33];
    const int b  = blockIdx.z;
    const int s0 = blockIdx.x * 32;
    const int d0 = blockIdx.y * 32;
    const float* Vb  = V  + (long long)b * SEQ * DMODEL;
    float*       Vtb = Vt + (long long)b * SEQ * DMODEL;
    const int x = threadIdx.x, y = threadIdx.y;   // 32 x 8
    #pragma unroll
    for (int i = 0; i < 32; i += 8)
        t[y + i][x] = Vb[(long long)(s0 + y + i) * DMODEL + d0 + x];
    __syncthreads();
    #pragma unroll
    for (int i = 0; i < 32; i += 8)
        Vtb[(long long)(d0 + y + i) * SEQ + s0 + x] = t[x][y + i];
}

// ---------------------------------------------------------------------------
// Row softmax in place (one 512-thread block per row of 4096)
// ---------------------------------------------------------------------------
__global__ __launch_bounds__(512)
void softmax_rows(float* __restrict__ S)
{
    float* p = S + (long long)blockIdx.x * SEQ;
    const int tid = threadIdx.x;

    float4 a = ((const float4*)p)[tid];
    float4 b = ((const float4*)p)[tid + 512];

    __shared__ float sred[16];
    __shared__ float sval;

    float m = fmaxf(fmaxf(fmaxf(a.x, a.y), fmaxf(a.z, a.w)),
                    fmaxf(fmaxf(b.x, b.y), fmaxf(b.z, b.w)));
    #pragma unroll
    for (int o = 16; o > 0; o >>= 1) m = fmaxf(m, __shfl_xor_sync(0xffffffffu, m, o));
    if ((tid & 31) == 0) sred[tid >> 5] = m;
    __syncthreads();
    if (tid < 32) {
        float x = (tid < 16) ? sred[tid] : __int_as_float(0xff800000);
        #pragma unroll
        for (int o = 8; o > 0; o >>= 1) x = fmaxf(x, __shfl_xor_sync(0xffffffffu, x, o));
        if (tid == 0) sval = x;
    }
    __syncthreads();
    const float rmax = sval;
    __syncthreads();

    a.x = expf(a.x - rmax); a.y = expf(a.y - rmax);
    a.z = expf(a.z - rmax); a.w = expf(a.w - rmax);
    b.x = expf(b.x - rmax); b.y = expf(b.y - rmax);
    b.z = expf(b.z - rmax); b.w = expf(b.w - rmax);

    float s = (a.x + a.y) + (a.z + a.w) + (b.x + b.y) + (b.z + b.w);
    #pragma unroll
    for (int o = 16; o > 0; o >>= 1) s += __shfl_xor_sync(0xffffffffu, s, o);
    if ((tid & 31) == 0) sred[tid >> 5] = s;
    __syncthreads();
    if (tid < 32) {
        float x = (tid < 16) ? sred[tid] : 0.f;
        #pragma unroll
        for (int o = 8; o > 0; o >>= 1) x += __shfl_xor_sync(0xffffffffu, x, o);
        if (tid == 0) sval = x;
    }
    __syncthreads();
    const float inv = 1.0f / sval;

    a.x *= inv; a.y *= inv; a.z *= inv; a.w *= inv;
    b.x *= inv; b.y *= inv; b.z *= inv; b.w *= inv;
    ((float4*)p)[tid]       = a;
    ((float4*)p)[tid + 512] = b;
}

// ---------------------------------------------------------------------------
// Launcher
// ---------------------------------------------------------------------------
extern "C" void kernel_launch(void* const* d_in, const int* in_sizes, int n_in,
                              void* d_out, int out_size)
{
    const float* query = (const float*)d_in[0];
    const float* value = (const float*)d_in[1];
    const float* Wq    = (const float*)d_in[2];
    const float* bq    = (const float*)d_in[3];
    const float* qkb   = (const float*)d_in[4];
    const float* Wv    = (const float*)d_in[5];
    const float* bv    = (const float*)d_in[6];
    float* out = (float*)d_out;

    float *pQ, *pV, *pVt, *pS;
    cudaGetSymbolAddress((void**)&pQ,  g_Q);
    cudaGetSymbolAddress((void**)&pV,  g_V);
    cudaGetSymbolAddress((void**)&pVt, g_Vt);
    cudaGetSymbolAddress((void**)&pS,  g_S);

    static bool attr_done = false;
    if (!attr_done) {
        cudaFuncSetAttribute(gemm_nt_mma,
                             cudaFuncAttributeMaxDynamicSharedMemorySize, SMEM_DYN);
        attr_done = true;
    }

    const int S = SEQ, D = DMODEL, B = BATCH;
    const long long SD = (long long)S * D;
    const long long SS = (long long)S * S;

    // 1) projections
    dim3 gp(D / BN, (B * S) / BM, 1);
    gemm_nt_mma<<<gp, THREADS, SMEM_DYN>>>(query, Wq, pQ, D, D, D, D,
                                           bq, qkb, 1.0f, 0, 0, 0);
    gemm_nt_mma<<<gp, THREADS, SMEM_DYN>>>(value, Wv, pV, D, D, D, D,
                                           bv, nullptr, 1.0f, 0, 0, 0);

    // 2) Vt[b,d,s] = V[b,s,d]
    transpose_v<<<dim3(S / 32, D / 32, B), dim3(32, 8)>>>(pV, pVt);

    // 3) scores: S[b] = Q[b]·V[b]^T / 8
    dim3 gs(S / BN, S / BM, B);
    gemm_nt_mma<<<gs, THREADS, SMEM_DYN>>>(pQ, pV, pS, D, D, D, S,
                                           nullptr, nullptr, 0.125f, SD, SD, SS);

    // 4) softmax rows in place
    softmax_rows<<<B * S, 512>>>(pS);

    // 5) out[b] = P[b]·Vt[b]^T
    dim3 go(D / BN, S / BM, B);
    gemm_nt_mma<<<go, THREADS, SMEM_DYN>>>(pS, pVt, out, S, S, S, D,
                                           nullptr, nullptr, 1.0f, SS, SD, SD);
}

// round 7
// speedup vs baseline: 3.1561x; 1.2322x over previous
#include <cuda_runtime.h>
#include <cuda_bf16.h>
#include <cstdint>

#define BATCH  4
#define SEQ    4096
#define DMODEL 1024

// GEMM: CTA 128x128, 256 threads (8 warps as 2x4), warp tile 64x32.
// K in chunks of 32; operands are pre-split bf16 hi/lo in gmem; cp.async
// double-buffered smem; fp32 accumulate via mma.sync m16n8k16 bf16.
#define BM 128
#define BN 128
#define THREADS 256
#define ROW_B   80                   // 32 bf16 (64B) + 16B pad per row
#define HALF_B  (128 * ROW_B)        // 10240
#define STAGE_B (4 * HALF_B)         // 40960 (Ah|Al|Bh|Bl)
#define SMEM_DYN (2 * STAGE_B)       // 81920 -> 2 CTAs/SM

// ---------------------------------------------------------------------------
// Scratch (device globals; allocation forbidden)
// ---------------------------------------------------------------------------
#define SD ((size_t)BATCH * SEQ * DMODEL)   // 16M
#define SS ((size_t)BATCH * SEQ * SEQ)      // 64M
__device__ __nv_bfloat16 g_xqh[SD], g_xql[SD];        // split(query)
__device__ __nv_bfloat16 g_xvh[SD], g_xvl[SD];        // split(value)
__device__ __nv_bfloat16 g_wqh[DMODEL*DMODEL], g_wql[DMODEL*DMODEL];
__device__ __nv_bfloat16 g_wvh[DMODEL*DMODEL], g_wvl[DMODEL*DMODEL];
__device__ __nv_bfloat16 g_Qh[SD], g_Ql[SD];          // Q proj split
__device__ float         g_V[SD];                     // V proj fp32
__device__ __nv_bfloat16 g_Vh[SD], g_Vl[SD];          // V proj split
__device__ __nv_bfloat16 g_Vth[SD], g_Vtl[SD];        // V^T split
__device__ float         g_S[SS];                     // scores fp32
__device__ __nv_bfloat16 g_Ph[SS], g_Pl[SS];          // softmax(P) split

// ---------------------------------------------------------------------------
// helpers
// ---------------------------------------------------------------------------
__device__ __forceinline__ uint32_t smem_u32(const void* p) {
    uint32_t a;
    asm("{ .reg .u64 t; cvta.to.shared.u64 t, %1; cvt.u32.u64 %0, t; }" : "=r"(a) : "l"(p));
    return a;
}
__device__ __forceinline__ void cpasync16(uint32_t dst, const void* src) {
    asm volatile("{ .reg .u64 g; cvta.to.global.u64 g, %1; "
                 "cp.async.cg.shared.global [%0], [g], 16; }"
                 :: "r"(dst), "l"(src) : "memory");
}
#define CP_COMMIT() asm volatile("cp.async.commit_group;" ::: "memory")
#define CP_WAIT(n)  asm volatile("cp.async.wait_group %0;" :: "n"(n) : "memory")

#define LDSM4(d, addr) \
    asm volatile("ldmatrix.sync.aligned.m8n8.x4.shared.b16 {%0,%1,%2,%3}, [%4];" \
        : "=r"((d)[0]), "=r"((d)[1]), "=r"((d)[2]), "=r"((d)[3]) : "r"(addr))

#define MMA_BF16(d, a, b0, b1v) \
    asm volatile("mma.sync.aligned.m16n8k16.row.col.f32.bf16.bf16.f32 " \
        "{%0,%1,%2,%3}, {%4,%5,%6,%7}, {%8,%9}, {%0,%1,%2,%3};" \
        : "+f"((d)[0]), "+f"((d)[1]), "+f"((d)[2]), "+f"((d)[3]) \
        : "r"((a)[0]), "r"((a)[1]), "r"((a)[2]), "r"((a)[3]), \
          "r"(b0), "r"(b1v))

__device__ __forceinline__ void split2(float x, float y, uint32_t& hi, uint32_t& lo) {
    __nv_bfloat16 hx = __float2bfloat16(x), hy = __float2bfloat16(y);
    __nv_bfloat162 hp(hx, hy);
    hi = *reinterpret_cast<uint32_t*>(&hp);
    __nv_bfloat162 lp = __floats2bfloat162_rn(x - __bfloat162float(hx),
                                              y - __bfloat162float(hy));
    lo = *reinterpret_cast<uint32_t*>(&lp);
}

// ---------------------------------------------------------------------------
// bf16 hi/lo 3-term NT GEMM:
//   C[m,n] = scale * sum_k A[m,k]*B[n,k] (+ b1[n] + b2[n])
// MODE bit0: write fp32 C ; MODE bit1: write bf16 split Ch/Cl
// ---------------------------------------------------------------------------
template<int MODE>
__global__ __launch_bounds__(THREADS, 2)
void gemm_nt_bf16(const __nv_bfloat16* __restrict__ Ah, const __nv_bfloat16* __restrict__ Al,
                  const __nv_bfloat16* __restrict__ Bh, const __nv_bfloat16* __restrict__ Bl,
                  float* __restrict__ C,
                  __nv_bfloat16* __restrict__ Ch, __nv_bfloat16* __restrict__ Cl,
                  int K, int ldc,
                  const float* __restrict__ b1, const float* __restrict__ b2,
                  float scale,
                  long long aB, long long bB, long long cB)
{
    extern __shared__ char smem[];
    const uint32_t sbase = smem_u32(smem);

    const int tid  = threadIdx.x;
    const int lane = tid & 31;
    const int w    = tid >> 5;     // 0..7
    const int wm   = w & 1;        // 2 m-positions of 64
    const int wn   = w >> 1;       // 4 n-positions of 32

    Ah += (long long)blockIdx.z * aB;  Al += (long long)blockIdx.z * aB;
    Bh += (long long)blockIdx.z * bB;  Bl += (long long)blockIdx.z * bB;
    const long long cOff = (long long)blockIdx.z * cB;
    const int m0 = blockIdx.y * BM;
    const int n0 = blockIdx.x * BN;

    // ldmatrix per-thread byte offsets within one 128x80B half-tile
    const uint32_t offA = (uint32_t)((wm * 64 + ((lane >> 3) & 1) * 8 + (lane & 7)) * ROW_B
                                     + ((lane >> 4) & 1) * 16);
    const uint32_t offB = (uint32_t)((wn * 32 + ((lane >> 4) & 1) * 8 + (lane & 7)) * ROW_B
                                     + ((lane >> 3) & 1) * 16);

    // cp.async mapping: thread covers rows r0 and r0+64, 16B chunk c16
    const int r0  = tid >> 2;       // 0..63
    const int c16 = tid & 3;        // 0..3
    const uint32_t d0 = (uint32_t)(r0 * ROW_B + c16 * 16);
    const uint32_t d1 = d0 + 64 * ROW_B;

    const __nv_bfloat16* pAh = Ah + (long long)(m0 + r0) * K + c16 * 8;
    const __nv_bfloat16* pAl = Al + (long long)(m0 + r0) * K + c16 * 8;
    const __nv_bfloat16* pBh = Bh + (long long)(n0 + r0) * K + c16 * 8;
    const __nv_bfloat16* pBl = Bl + (long long)(n0 + r0) * K + c16 * 8;
    const long long rstep = 64LL * K;

    float acc[4][4][4];
    #pragma unroll
    for (int i = 0; i < 4; ++i)
        #pragma unroll
        for (int j = 0; j < 4; ++j)
            #pragma unroll
            for (int q = 0; q < 4; ++q) acc[i][j][q] = 0.f;

    const int nc = K >> 5;

    // stage issue
    auto issue = [&](int c, int s) {
        const uint32_t sb = sbase + (uint32_t)s * STAGE_B;
        const int ko = c * 32;
        cpasync16(sb + d0,              pAh + ko);
        cpasync16(sb + d1,              pAh + ko + rstep);
        cpasync16(sb + HALF_B + d0,     pAl + ko);
        cpasync16(sb + HALF_B + d1,     pAl + ko + rstep);
        cpasync16(sb + 2*HALF_B + d0,   pBh + ko);
        cpasync16(sb + 2*HALF_B + d1,   pBh + ko + rstep);
        cpasync16(sb + 3*HALF_B + d0,   pBl + ko);
        cpasync16(sb + 3*HALF_B + d1,   pBl + ko + rstep);
    };

    issue(0, 0); CP_COMMIT();

    for (int c = 0; c < nc; ++c) {
        if (c + 1 < nc) { issue(c + 1, (c + 1) & 1); CP_COMMIT(); CP_WAIT(1); }
        else            { CP_WAIT(0); }
        __syncthreads();

        const uint32_t base = sbase + (uint32_t)(c & 1) * STAGE_B;
        #pragma unroll
        for (int kk2 = 0; kk2 < 2; ++kk2) {
            const uint32_t kb = kk2 * 32;   // 16 bf16 = 32B
            uint32_t ah[4][4], bh[2][4];
            #pragma unroll
            for (int mi = 0; mi < 4; ++mi) LDSM4(ah[mi], base + offA + mi * (16*ROW_B) + kb);
            #pragma unroll
            for (int nt = 0; nt < 2; ++nt) LDSM4(bh[nt], base + 2*HALF_B + offB + nt * (16*ROW_B) + kb);
            // hi * hi
            #pragma unroll
            for (int mi = 0; mi < 4; ++mi)
                #pragma unroll
                for (int nt = 0; nt < 2; ++nt)
                    #pragma unroll
                    for (int nh = 0; nh < 2; ++nh)
                        MMA_BF16(acc[mi][nt*2+nh], ah[mi], bh[nt][nh*2], bh[nt][nh*2+1]);
            // lo * hi
            {
                uint32_t al[4][4];
                #pragma unroll
                for (int mi = 0; mi < 4; ++mi) LDSM4(al[mi], base + HALF_B + offA + mi * (16*ROW_B) + kb);
                #pragma unroll
                for (int mi = 0; mi < 4; ++mi)
                    #pragma unroll
                    for (int nt = 0; nt < 2; ++nt)
                        #pragma unroll
                        for (int nh = 0; nh < 2; ++nh)
                            MMA_BF16(acc[mi][nt*2+nh], al[mi], bh[nt][nh*2], bh[nt][nh*2+1]);
            }
            // hi * lo
            {
                uint32_t bl[2][4];
                #pragma unroll
                for (int nt = 0; nt < 2; ++nt) LDSM4(bl[nt], base + 3*HALF_B + offB + nt * (16*ROW_B) + kb);
                #pragma unroll
                for (int mi = 0; mi < 4; ++mi)
                    #pragma unroll
                    for (int nt = 0; nt < 2; ++nt)
                        #pragma unroll
                        for (int nh = 0; nh < 2; ++nh)
                            MMA_BF16(acc[mi][nt*2+nh], ah[mi], bl[nt][nh*2], bl[nt][nh*2+1]);
            }
        }
        __syncthreads();
    }

    // epilogue
    const int gid = lane >> 2;
    const int tig = lane & 3;
    #pragma unroll
    for (int mi = 0; mi < 4; ++mi) {
        const int row = m0 + wm * 64 + mi * 16 + gid;
        #pragma unroll
        for (int ni = 0; ni < 4; ++ni) {
            const int col = n0 + wn * 32 + ni * 8 + tig * 2;
            float bb0 = 0.f, bb1 = 0.f;
            if (b1) { bb0 += b1[col]; bb1 += b1[col + 1]; }
            if (b2) { bb0 += b2[col]; bb1 += b2[col + 1]; }
            float2 o0, o1;
            o0.x = acc[mi][ni][0] * scale + bb0;
            o0.y = acc[mi][ni][1] * scale + bb1;
            o1.x = acc[mi][ni][2] * scale + bb0;
            o1.y = acc[mi][ni][3] * scale + bb1;
            const long long i0 = cOff + (long long)row * ldc + col;
            const long long i1 = i0 + 8LL * ldc;
            if (MODE & 1) {
                *(float2*)(C + i0) = o0;
                *(float2*)(C + i1) = o1;
            }
            if (MODE & 2) {
                uint32_t h, l;
                split2(o0.x, o0.y, h, l);
                *(uint32_t*)(Ch + i0) = h; *(uint32_t*)(Cl + i0) = l;
                split2(o1.x, o1.y, h, l);
                *(uint32_t*)(Ch + i1) = h; *(uint32_t*)(Cl + i1) = l;
            }
        }
    }
}

// ---------------------------------------------------------------------------
// split fp32 -> bf16 hi/lo (vectorized)
// ---------------------------------------------------------------------------
__global__ __launch_bounds__(256)
void split_f32(const float4* __restrict__ in, uint2* __restrict__ hi,
               uint2* __restrict__ lo, int n4)
{
    int i = blockIdx.x * 256 + threadIdx.x;
    if (i >= n4) return;
    float4 v = in[i];
    uint32_t h0, l0, h1, l1;
    split2(v.x, v.y, h0, l0);
    split2(v.z, v.w, h1, l1);
    hi[i] = make_uint2(h0, h1);
    lo[i] = make_uint2(l0, l1);
}

// ---------------------------------------------------------------------------
// V transpose + split: Vt{h,l}[b][d][s] = split(V[b][s][d])
// ---------------------------------------------------------------------------
__global__ __launch_bounds__(256)
void transpose_split(const float* __restrict__ V,
                     __nv_bfloat16* __restrict__ Vth, __nv_bfloat16* __restrict__ Vtl)
{
    __shared__ float t[32][33];
    const int b  = blockIdx.z;
    const int s0 = blockIdx.x * 32;
    const int d0 = blockIdx.y * 32;
    const float* Vb = V + (long long)b * SEQ * DMODEL;
    __nv_bfloat16* Hh = Vth + (long long)b * SEQ * DMODEL;
    __nv_bfloat16* Hl = Vtl + (long long)b * SEQ * DMODEL;
    const int x = threadIdx.x, y = threadIdx.y;   // 32 x 8
    #pragma unroll
    for (int i = 0; i < 32; i += 8)
        t[y + i][x] = Vb[(long long)(s0 + y + i) * DMODEL + d0 + x];
    __syncthreads();
    #pragma unroll
    for (int i = 0; i < 32; i += 8) {
        float v = t[x][y + i];
        __nv_bfloat16 h = __float2bfloat16(v);
        Hh[(long long)(d0 + y + i) * SEQ + s0 + x] = h;
        Hl[(long long)(d0 + y + i) * SEQ + s0 + x] =
            __float2bfloat16(v - __bfloat162float(h));
    }
}

// ---------------------------------------------------------------------------
// Row softmax: reads fp32 S row, writes bf16 hi/lo P row (halves gmem writes)
// ---------------------------------------------------------------------------
__global__ __launch_bounds__(512)
void softmax_rows(const float* __restrict__ S,
                  __nv_bfloat16* __restrict__ Ph, __nv_bfloat16* __restrict__ Pl)
{
    const float* p = S + (long long)blockIdx.x * SEQ;
    const int tid = threadIdx.x;

    float4 a = ((const float4*)p)[tid];
    float4 b = ((const float4*)p)[tid + 512];

    __shared__ float sred[16];
    __shared__ float sval;

    float m = fmaxf(fmaxf(fmaxf(a.x, a.y), fmaxf(a.z, a.w)),
                    fmaxf(fmaxf(b.x, b.y), fmaxf(b.z, b.w)));
    #pragma unroll
    for (int o = 16; o > 0; o >>= 1) m = fmaxf(m, __shfl_xor_sync(0xffffffffu, m, o));
    if ((tid & 31) == 0) sred[tid >> 5] = m;
    __syncthreads();
    if (tid < 32) {
        float x = (tid < 16) ? sred[tid] : __int_as_float(0xff800000);
        #pragma unroll
        for (int o = 8; o > 0; o >>= 1) x = fmaxf(x, __shfl_xor_sync(0xffffffffu, x, o));
        if (tid == 0) sval = x;
    }
    __syncthreads();
    const float rmax = sval;
    __syncthreads();

    a.x = expf(a.x - rmax); a.y = expf(a.y - rmax);
    a.z = expf(a.z - rmax); a.w = expf(a.w - rmax);
    b.x = expf(b.x - rmax); b.y = expf(b.y - rmax);
    b.z = expf(b.z - rmax); b.w = expf(b.w - rmax);

    float s = (a.x + a.y) + (a.z + a.w) + (b.x + b.y) + (b.z + b.w);
    #pragma unroll
    for (int o = 16; o > 0; o >>= 1) s += __shfl_xor_sync(0xffffffffu, s, o);
    if ((tid & 31) == 0) sred[tid >> 5] = s;
    __syncthreads();
    if (tid < 32) {
        float x = (tid < 16) ? sred[tid] : 0.f;
        #pragma unroll
        for (int o = 8; o > 0; o >>= 1) x += __shfl_xor_sync(0xffffffffu, x, o);
        if (tid == 0) sval = x;
    }
    __syncthreads();
    const float inv = 1.0f / sval;

    a.x *= inv; a.y *= inv; a.z *= inv; a.w *= inv;
    b.x *= inv; b.y *= inv; b.z *= inv; b.w *= inv;

    const long long rb = (long long)blockIdx.x * (SEQ / 4);   // uint2 index base
    uint32_t h0, l0, h1, l1;
    split2(a.x, a.y, h0, l0); split2(a.z, a.w, h1, l1);
    ((uint2*)Ph)[rb + tid] = make_uint2(h0, h1);
    ((uint2*)Pl)[rb + tid] = make_uint2(l0, l1);
    split2(b.x, b.y, h0, l0); split2(b.z, b.w, h1, l1);
    ((uint2*)Ph)[rb + 512 + tid] = make_uint2(h0, h1);
    ((uint2*)Pl)[rb + 512 + tid] = make_uint2(l0, l1);
}

// ---------------------------------------------------------------------------
// Launcher
// ---------------------------------------------------------------------------
extern "C" void kernel_launch(void* const* d_in, const int* in_sizes, int n_in,
                              void* d_out, int out_size)
{
    const float* query = (const float*)d_in[0];
    const float* value = (const float*)d_in[1];
    const float* Wq    = (const float*)d_in[2];
    const float* bq    = (const float*)d_in[3];
    const float* qkb   = (const float*)d_in[4];
    const float* Wv    = (const float*)d_in[5];
    const float* bv    = (const float*)d_in[6];
    float* out = (float*)d_out;

    __nv_bfloat16 *xqh, *xql, *xvh, *xvl, *wqh, *wql, *wvh, *wvl;
    __nv_bfloat16 *Qh, *Ql, *Vh, *Vl, *Vth, *Vtl, *Ph, *Pl;
    float *V, *Sc;
    cudaGetSymbolAddress((void**)&xqh, g_xqh); cudaGetSymbolAddress((void**)&xql, g_xql);
    cudaGetSymbolAddress((void**)&xvh, g_xvh); cudaGetSymbolAddress((void**)&xvl, g_xvl);
    cudaGetSymbolAddress((void**)&wqh, g_wqh); cudaGetSymbolAddress((void**)&wql, g_wql);
    cudaGetSymbolAddress((void**)&wvh, g_wvh); cudaGetSymbolAddress((void**)&wvl, g_wvl);
    cudaGetSymbolAddress((void**)&Qh,  g_Qh);  cudaGetSymbolAddress((void**)&Ql,  g_Ql);
    cudaGetSymbolAddress((void**)&V,   g_V);
    cudaGetSymbolAddress((void**)&Vh,  g_Vh);  cudaGetSymbolAddress((void**)&Vl,  g_Vl);
    cudaGetSymbolAddress((void**)&Vth, g_Vth); cudaGetSymbolAddress((void**)&Vtl, g_Vtl);
    cudaGetSymbolAddress((void**)&Sc,  g_S);
    cudaGetSymbolAddress((void**)&Ph,  g_Ph);  cudaGetSymbolAddress((void**)&Pl,  g_Pl);

    static bool attr_done = false;
    if (!attr_done) {
        cudaFuncSetAttribute(gemm_nt_bf16<1>, cudaFuncAttributeMaxDynamicSharedMemorySize, SMEM_DYN);
        cudaFuncSetAttribute(gemm_nt_bf16<2>, cudaFuncAttributeMaxDynamicSharedMemorySize, SMEM_DYN);
        cudaFuncSetAttribute(gemm_nt_bf16<3>, cudaFuncAttributeMaxDynamicSharedMemorySize, SMEM_DYN);
        attr_done = true;
    }

    const int S = SEQ, D = DMODEL, B = BATCH;
    const long long sd = (long long)S * D;
    const long long ss = (long long)S * S;

    // 0) split raw inputs + weights to bf16 hi/lo
    split_f32<<<(B*S*D/4 + 255)/256, 256>>>((const float4*)query, (uint2*)xqh, (uint2*)xql, B*S*D/4);
    split_f32<<<(B*S*D/4 + 255)/256, 256>>>((const float4*)value, (uint2*)xvh, (uint2*)xvl, B*S*D/4);
    split_f32<<<(D*D/4 + 255)/256, 256>>>((const float4*)Wq, (uint2*)wqh, (uint2*)wql, D*D/4);
    split_f32<<<(D*D/4 + 255)/256, 256>>>((const float4*)Wv, (uint2*)wvh, (uint2*)wvl, D*D/4);

    // 1) projections (Q: split only; V: fp32 + split)
    dim3 gp(D / BN, (B * S) / BM, 1);
    gemm_nt_bf16<2><<<gp, THREADS, SMEM_DYN>>>(xqh, xql, wqh, wql,
                                               nullptr, Qh, Ql, D, D,
                                               bq, qkb, 1.0f, 0, 0, 0);
    gemm_nt_bf16<3><<<gp, THREADS, SMEM_DYN>>>(xvh, xvl, wvh, wvl,
                                               V, Vh, Vl, D, D,
                                               bv, nullptr, 1.0f, 0, 0, 0);

    // 2) Vt split
    transpose_split<<<dim3(S / 32, D / 32, B), dim3(32, 8)>>>(V, Vth, Vtl);

    // 3) scores: S[b] = Q[b]·V[b]^T / 8  (fp32 out)
    dim3 gs(S / BN, S / BM, B);
    gemm_nt_bf16<1><<<gs, THREADS, SMEM_DYN>>>(Qh, Ql, Vh, Vl,
                                               Sc, nullptr, nullptr, D, S,
                                               nullptr, nullptr, 0.125f, sd, sd, ss);

    // 4) softmax -> P hi/lo
    softmax_rows<<<B * S, 512>>>(Sc, Ph, Pl);

    // 5) out[b] = P[b]·Vt[b]^T  (fp32 out)
    dim3 go(D / BN, S / BM, B);
    gemm_nt_bf16<1><<<go, THREADS, SMEM_DYN>>>(Ph, Pl, Vth, Vtl,
                                               out, nullptr, nullptr, S, D,
                                               nullptr, nullptr, 1.0f, ss, sd, sd);
}

// round 8
// speedup vs baseline: 3.3261x; 1.0539x over previous
#include <cuda_runtime.h>
#include <cuda_bf16.h>
#include <cuda_fp16.h>
#include <cstdint>

#define BATCH  4
#define SEQ    4096
#define DMODEL 1024

// GEMM: CTA 128x256, 256 threads (8 warps as 2x4), warp tile 64x64.
// K in chunks of 32; pre-split 16-bit operands in gmem; 3-stage cp.async.
#define BM 128
#define BN 256
#define THREADS 256
#define ROW_B   80                    // 32 elems (64B) + 16B pad
#define A_HALF  (128 * ROW_B)         // 10240
#define B_HALF  (256 * ROW_B)         // 20480
#define OFF_AL  A_HALF                // 10240
#define OFF_BH  (2 * A_HALF)          // 20480
#define OFF_BL  (2 * A_HALF + B_HALF) // 40960
#define STAGE_B (2 * A_HALF + 2 * B_HALF)  // 61440
#define SMEM_DYN (3 * STAGE_B)        // 184320

// ---------------------------------------------------------------------------
// Scratch (device globals; allocation forbidden)
// ---------------------------------------------------------------------------
#define SD ((size_t)BATCH * SEQ * DMODEL)   // 16M
#define SS ((size_t)BATCH * SEQ * SEQ)      // 64M
__device__ uint16_t g_xqh[SD], g_xql[SD];            // split(query) bf16
__device__ uint16_t g_xvh[SD], g_xvl[SD];            // split(value) bf16
__device__ uint16_t g_wqh[DMODEL*DMODEL], g_wql[DMODEL*DMODEL];
__device__ uint16_t g_wvh[DMODEL*DMODEL], g_wvl[DMODEL*DMODEL];
__device__ uint16_t g_Qh[SD], g_Ql[SD];              // Q proj split bf16
__device__ float    g_V[SD];                         // V proj fp32
__device__ uint16_t g_Vh[SD], g_Vl[SD];              // V proj split bf16
__device__ uint16_t g_Vth[SD], g_Vtl[SD];            // V^T split fp16
__device__ float    g_S[SS];                         // scores fp32
__device__ uint16_t g_Ph[SS];                        // softmax(P) fp16

// ---------------------------------------------------------------------------
// helpers
// ---------------------------------------------------------------------------
__device__ __forceinline__ uint32_t smem_u32(const void* p) {
    uint32_t a;
    asm("{ .reg .u64 t; cvta.to.shared.u64 t, %1; cvt.u32.u64 %0, t; }" : "=r"(a) : "l"(p));
    return a;
}
__device__ __forceinline__ void cpasync16(uint32_t dst, const void* src) {
    asm volatile("{ .reg .u64 g; cvta.to.global.u64 g, %1; "
                 "cp.async.cg.shared.global [%0], [g], 16; }"
                 :: "r"(dst), "l"(src) : "memory");
}
#define CP_COMMIT() asm volatile("cp.async.commit_group;" ::: "memory")
#define CP_WAIT(n)  asm volatile("cp.async.wait_group %0;" :: "n"(n) : "memory")

#define LDSM4(d, addr) \
    asm volatile("ldmatrix.sync.aligned.m8n8.x4.shared.b16 {%0,%1,%2,%3}, [%4];" \
        : "=r"((d)[0]), "=r"((d)[1]), "=r"((d)[2]), "=r"((d)[3]) : "r"(addr))

template<int FP16>
__device__ __forceinline__ void mma16(float* d, const uint32_t* a,
                                      uint32_t b0, uint32_t b1v) {
    if constexpr (FP16) {
        asm volatile("mma.sync.aligned.m16n8k16.row.col.f32.f16.f16.f32 "
            "{%0,%1,%2,%3}, {%4,%5,%6,%7}, {%8,%9}, {%0,%1,%2,%3};"
            : "+f"(d[0]), "+f"(d[1]), "+f"(d[2]), "+f"(d[3])
            : "r"(a[0]), "r"(a[1]), "r"(a[2]), "r"(a[3]), "r"(b0), "r"(b1v));
    } else {
        asm volatile("mma.sync.aligned.m16n8k16.row.col.f32.bf16.bf16.f32 "
            "{%0,%1,%2,%3}, {%4,%5,%6,%7}, {%8,%9}, {%0,%1,%2,%3};"
            : "+f"(d[0]), "+f"(d[1]), "+f"(d[2]), "+f"(d[3])
            : "r"(a[0]), "r"(a[1]), "r"(a[2]), "r"(a[3]), "r"(b0), "r"(b1v));
    }
}

__device__ __forceinline__ void split2(float x, float y, uint32_t& hi, uint32_t& lo) {
    __nv_bfloat16 hx = __float2bfloat16(x), hy = __float2bfloat16(y);
    __nv_bfloat162 hp(hx, hy);
    hi = *reinterpret_cast<uint32_t*>(&hp);
    __nv_bfloat162 lp = __floats2bfloat162_rn(x - __bfloat162float(hx),
                                              y - __bfloat162float(hy));
    lo = *reinterpret_cast<uint32_t*>(&lp);
}

// ---------------------------------------------------------------------------
// 16-bit split NT GEMM:  C[m,n] = scale * sum_k A[m,k]*B[n,k] (+ b1 + b2)
// TERMS=3: Ah*Bh + Ah*Bl + Al*Bh   (bf16 3-term)
// TERMS=2: Ah*Bh + Ah*Bl           (fp16, A single / B split)
// MODE bit0: fp32 C ; bit1: bf16 split Ch/Cl
// ---------------------------------------------------------------------------
template<int TERMS, int FP16, int MODE>
__global__ __launch_bounds__(THREADS, 1)
void gemm_nt(const uint16_t* __restrict__ Ah, const uint16_t* __restrict__ Al,
             const uint16_t* __restrict__ Bh, const uint16_t* __restrict__ Bl,
             float* __restrict__ C, uint16_t* __restrict__ Ch, uint16_t* __restrict__ Cl,
             int K, int ldc,
             const float* __restrict__ b1, const float* __restrict__ b2,
             float scale,
             long long aB, long long bB, long long cB)
{
    extern __shared__ char smem[];
    const uint32_t sbase = smem_u32(smem);
    const int tid = threadIdx.x, lane = tid & 31, w = tid >> 5;
    const int wm = w & 1, wn = w >> 1;

    Ah += (long long)blockIdx.z * aB;
    if (TERMS == 3) Al += (long long)blockIdx.z * aB;
    Bh += (long long)blockIdx.z * bB;
    Bl += (long long)blockIdx.z * bB;
    const long long cOff = (long long)blockIdx.z * cB;
    const int m0 = blockIdx.y * BM;
    const int n0 = blockIdx.x * BN;

    const uint32_t offA = (uint32_t)((wm * 64 + ((lane >> 3) & 1) * 8 + (lane & 7)) * ROW_B
                                     + ((lane >> 4) & 1) * 16);
    const uint32_t offB = (uint32_t)((wn * 64 + ((lane >> 4) & 1) * 8 + (lane & 7)) * ROW_B
                                     + ((lane >> 3) & 1) * 16);

    float acc[4][8][4];
    #pragma unroll
    for (int i = 0; i < 4; ++i)
        #pragma unroll
        for (int j = 0; j < 8; ++j)
            #pragma unroll
            for (int q = 0; q < 4; ++q) acc[i][j][q] = 0.f;

    const int nc = K >> 5;

    auto issue = [&](int c, int s) {
        const uint32_t sb = sbase + (uint32_t)s * STAGE_B;
        const int k0 = c * 32;
        #pragma unroll
        for (int i = 0; i < 2; ++i) {                 // A: 512 16B-chunks
            int idx = tid + i * 256;
            int row = idx >> 2, cc = idx & 3;
            const uint32_t d = sb + row * ROW_B + cc * 16;
            const long long g = (long long)(m0 + row) * K + k0 + cc * 8;
            cpasync16(d, Ah + g);
            if (TERMS == 3) cpasync16(d + OFF_AL, Al + g);
        }
        #pragma unroll
        for (int i = 0; i < 4; ++i) {                 // B: 1024 16B-chunks
            int idx = tid + i * 256;
            int row = idx >> 2, cc = idx & 3;
            const uint32_t d = sb + row * ROW_B + cc * 16;
            const long long g = (long long)(n0 + row) * K + k0 + cc * 8;
            cpasync16(d + OFF_BH, Bh + g);
            cpasync16(d + OFF_BL, Bl + g);
        }
    };

    issue(0, 0); CP_COMMIT();
    issue(1, 1); CP_COMMIT();

    int st = 0;       // compute stage
    int si = 2;       // next issue stage
    for (int c = 0; c < nc; ++c) {
        if (c == nc - 1) { CP_WAIT(0); } else { CP_WAIT(1); }
        __syncthreads();

        const uint32_t base = sbase + (uint32_t)st * STAGE_B;
        #pragma unroll
        for (int kk2 = 0; kk2 < 2; ++kk2) {
            const uint32_t kb = kk2 * 32;
            uint32_t ah[4][4], bhf[4][4];
            #pragma unroll
            for (int mi = 0; mi < 4; ++mi) LDSM4(ah[mi], base + offA + mi * (16 * ROW_B) + kb);
            #pragma unroll
            for (int nt = 0; nt < 4; ++nt) LDSM4(bhf[nt], base + OFF_BH + offB + nt * (16 * ROW_B) + kb);
            // hi * hi
            #pragma unroll
            for (int mi = 0; mi < 4; ++mi)
                #pragma unroll
                for (int nt = 0; nt < 4; ++nt)
                    #pragma unroll
                    for (int nh = 0; nh < 2; ++nh)
                        mma16<FP16>(acc[mi][nt * 2 + nh], ah[mi], bhf[nt][nh * 2], bhf[nt][nh * 2 + 1]);
            // hi * lo
            {
                uint32_t blf[4][4];
                #pragma unroll
                for (int nt = 0; nt < 4; ++nt) LDSM4(blf[nt], base + OFF_BL + offB + nt * (16 * ROW_B) + kb);
                #pragma unroll
                for (int mi = 0; mi < 4; ++mi)
                    #pragma unroll
                    for (int nt = 0; nt < 4; ++nt)
                        #pragma unroll
                        for (int nh = 0; nh < 2; ++nh)
                            mma16<FP16>(acc[mi][nt * 2 + nh], ah[mi], blf[nt][nh * 2], blf[nt][nh * 2 + 1]);
            }
            // lo * hi
            if constexpr (TERMS == 3) {
                uint32_t alf[4][4];
                #pragma unroll
                for (int mi = 0; mi < 4; ++mi) LDSM4(alf[mi], base + OFF_AL + offA + mi * (16 * ROW_B) + kb);
                #pragma unroll
                for (int mi = 0; mi < 4; ++mi)
                    #pragma unroll
                    for (int nt = 0; nt < 4; ++nt)
                        #pragma unroll
                        for (int nh = 0; nh < 2; ++nh)
                            mma16<FP16>(acc[mi][nt * 2 + nh], alf[mi], bhf[nt][nh * 2], bhf[nt][nh * 2 + 1]);
            }
        }

        if (c + 2 < nc) { issue(c + 2, si); CP_COMMIT(); }
        if (++st == 3) st = 0;
        if (++si == 3) si = 0;
    }

    // epilogue
    const int gid = lane >> 2, tig = lane & 3;
    #pragma unroll
    for (int mi = 0; mi < 4; ++mi) {
        const int row = m0 + wm * 64 + mi * 16 + gid;
        #pragma unroll
        for (int ni = 0; ni < 8; ++ni) {
            const int col = n0 + wn * 64 + ni * 8 + tig * 2;
            float bb0 = 0.f, bb1 = 0.f;
            if (b1) { bb0 += b1[col]; bb1 += b1[col + 1]; }
            if (b2) { bb0 += b2[col]; bb1 += b2[col + 1]; }
            float2 o0, o1;
            o0.x = acc[mi][ni][0] * scale + bb0;
            o0.y = acc[mi][ni][1] * scale + bb1;
            o1.x = acc[mi][ni][2] * scale + bb0;
            o1.y = acc[mi][ni][3] * scale + bb1;
            const long long i0 = cOff + (long long)row * ldc + col;
            const long long i1 = i0 + 8LL * ldc;
            if constexpr (MODE & 1) {
                *(float2*)(C + i0) = o0;
                *(float2*)(C + i1) = o1;
            }
            if constexpr (MODE & 2) {
                uint32_t h, l;
                split2(o0.x, o0.y, h, l);
                *(uint32_t*)(Ch + i0) = h; *(uint32_t*)(Cl + i0) = l;
                split2(o1.x, o1.y, h, l);
                *(uint32_t*)(Ch + i1) = h; *(uint32_t*)(Cl + i1) = l;
            }
        }
    }
}

// ---------------------------------------------------------------------------
// split fp32 -> bf16 hi/lo (vectorized)
// ---------------------------------------------------------------------------
__global__ __launch_bounds__(256)
void split_f32(const float4* __restrict__ in, uint2* __restrict__ hi,
               uint2* __restrict__ lo, int n4)
{
    int i = blockIdx.x * 256 + threadIdx.x;
    if (i >= n4) return;
    float4 v = in[i];
    uint32_t h0, l0, h1, l1;
    split2(v.x, v.y, h0, l0);
    split2(v.z, v.w, h1, l1);
    hi[i] = make_uint2(h0, h1);
    lo[i] = make_uint2(l0, l1);
}

// ---------------------------------------------------------------------------
// V transpose + fp16 split: Vt{h,l}[b][d][s] = split_f16(V[b][s][d])
// ---------------------------------------------------------------------------
__global__ __launch_bounds__(256)
void transpose_split(const float* __restrict__ V,
                     uint16_t* __restrict__ Vth, uint16_t* __restrict__ Vtl)
{
    __shared__ float t[32][33];
    const int b  = blockIdx.z;
    const int s0 = blockIdx.x * 32;
    const int d0 = blockIdx.y * 32;
    const float* Vb = V + (long long)b * SEQ * DMODEL;
    uint16_t* Hh = Vth + (long long)b * SEQ * DMODEL;
    uint16_t* Hl = Vtl + (long long)b * SEQ * DMODEL;
    const int x = threadIdx.x, y = threadIdx.y;   // 32 x 8
    #pragma unroll
    for (int i = 0; i < 32; i += 8)
        t[y + i][x] = Vb[(long long)(s0 + y + i) * DMODEL + d0 + x];
    __syncthreads();
    #pragma unroll
    for (int i = 0; i < 32; i += 8) {
        float v = t[x][y + i];
        __half h = __float2half_rn(v);
        __half l = __float2half_rn(v - __half2float(h));
        Hh[(long long)(d0 + y + i) * SEQ + s0 + x] = *reinterpret_cast<uint16_t*>(&h);
        Hl[(long long)(d0 + y + i) * SEQ + s0 + x] = *reinterpret_cast<uint16_t*>(&l);
    }
}

// ---------------------------------------------------------------------------
// Row softmax: fp32 S row in, fp16 P row out
// ---------------------------------------------------------------------------
__global__ __launch_bounds__(512)
void softmax_rows(const float* __restrict__ S, uint16_t* __restrict__ Ph)
{
    const float* p = S + (long long)blockIdx.x * SEQ;
    const int tid = threadIdx.x;

    float4 a = ((const float4*)p)[tid];
    float4 b = ((const float4*)p)[tid + 512];

    __shared__ float sred[16];
    __shared__ float sval;

    float m = fmaxf(fmaxf(fmaxf(a.x, a.y), fmaxf(a.z, a.w)),
                    fmaxf(fmaxf(b.x, b.y), fmaxf(b.z, b.w)));
    #pragma unroll
    for (int o = 16; o > 0; o >>= 1) m = fmaxf(m, __shfl_xor_sync(0xffffffffu, m, o));
    if ((tid & 31) == 0) sred[tid >> 5] = m;
    __syncthreads();
    if (tid < 32) {
        float x = (tid < 16) ? sred[tid] : __int_as_float(0xff800000);
        #pragma unroll
        for (int o = 8; o > 0; o >>= 1) x = fmaxf(x, __shfl_xor_sync(0xffffffffu, x, o));
        if (tid == 0) sval = x;
    }
    __syncthreads();
    const float rmax = sval;
    __syncthreads();

    a.x = expf(a.x - rmax); a.y = expf(a.y - rmax);
    a.z = expf(a.z - rmax); a.w = expf(a.w - rmax);
    b.x = expf(b.x - rmax); b.y = expf(b.y - rmax);
    b.z = expf(b.z - rmax); b.w = expf(b.w - rmax);

    float s = (a.x + a.y) + (a.z + a.w) + (b.x + b.y) + (b.z + b.w);
    #pragma unroll
    for (int o = 16; o > 0; o >>= 1) s += __shfl_xor_sync(0xffffffffu, s, o);
    if ((tid & 31) == 0) sred[tid >> 5] = s;
    __syncthreads();
    if (tid < 32) {
        float x = (tid < 16) ? sred[tid] : 0.f;
        #pragma unroll
        for (int o = 8; o > 0; o >>= 1) x += __shfl_xor_sync(0xffffffffu, x, o);
        if (tid == 0) sval = x;
    }
    __syncthreads();
    const float inv = 1.0f / sval;

    __half2 p0 = __floats2half2_rn(a.x * inv, a.y * inv);
    __half2 p1 = __floats2half2_rn(a.z * inv, a.w * inv);
    __half2 p2 = __floats2half2_rn(b.x * inv, b.y * inv);
    __half2 p3 = __floats2half2_rn(b.z * inv, b.w * inv);

    const long long rb = (long long)blockIdx.x * (SEQ / 4);
    ((uint2*)Ph)[rb + tid]       = make_uint2(*reinterpret_cast<uint32_t*>(&p0),
                                              *reinterpret_cast<uint32_t*>(&p1));
    ((uint2*)Ph)[rb + 512 + tid] = make_uint2(*reinterpret_cast<uint32_t*>(&p2),
                                              *reinterpret_cast<uint32_t*>(&p3));
}

// ---------------------------------------------------------------------------
// Launcher
// ---------------------------------------------------------------------------
extern "C" void kernel_launch(void* const* d_in, const int* in_sizes, int n_in,
                              void* d_out, int out_size)
{
    const float* query = (const float*)d_in[0];
    const float* value = (const float*)d_in[1];
    const float* Wq    = (const float*)d_in[2];
    const float* bq    = (const float*)d_in[3];
    const float* qkb   = (const float*)d_in[4];
    const float* Wv    = (const float*)d_in[5];
    const float* bv    = (const float*)d_in[6];
    float* out = (float*)d_out;

    uint16_t *xqh, *xql, *xvh, *xvl, *wqh, *wql, *wvh, *wvl;
    uint16_t *Qh, *Ql, *Vh, *Vl, *Vth, *Vtl, *Ph;
    float *V, *Sc;
    cudaGetSymbolAddress((void**)&xqh, g_xqh); cudaGetSymbolAddress((void**)&xql, g_xql);
    cudaGetSymbolAddress((void**)&xvh, g_xvh); cudaGetSymbolAddress((void**)&xvl, g_xvl);
    cudaGetSymbolAddress((void**)&wqh, g_wqh); cudaGetSymbolAddress((void**)&wql, g_wql);
    cudaGetSymbolAddress((void**)&wvh, g_wvh); cudaGetSymbolAddress((void**)&wvl, g_wvl);
    cudaGetSymbolAddress((void**)&Qh,  g_Qh);  cudaGetSymbolAddress((void**)&Ql,  g_Ql);
    cudaGetSymbolAddress((void**)&V,   g_V);
    cudaGetSymbolAddress((void**)&Vh,  g_Vh);  cudaGetSymbolAddress((void**)&Vl,  g_Vl);
    cudaGetSymbolAddress((void**)&Vth, g_Vth); cudaGetSymbolAddress((void**)&Vtl, g_Vtl);
    cudaGetSymbolAddress((void**)&Sc,  g_S);
    cudaGetSymbolAddress((void**)&Ph,  g_Ph);

    static bool attr_done = false;
    if (!attr_done) {
        cudaFuncSetAttribute(gemm_nt<3,0,1>, cudaFuncAttributeMaxDynamicSharedMemorySize, SMEM_DYN);
        cudaFuncSetAttribute(gemm_nt<3,0,2>, cudaFuncAttributeMaxDynamicSharedMemorySize, SMEM_DYN);
        cudaFuncSetAttribute(gemm_nt<3,0,3>, cudaFuncAttributeMaxDynamicSharedMemorySize, SMEM_DYN);
        cudaFuncSetAttribute(gemm_nt<2,1,1>, cudaFuncAttributeMaxDynamicSharedMemorySize, SMEM_DYN);
        attr_done = true;
    }

    const int S = SEQ, D = DMODEL, B = BATCH;
    const long long sd = (long long)S * D;
    const long long ss = (long long)S * S;

    // 0) split raw inputs + weights to bf16 hi/lo
    split_f32<<<(B*S*D/4 + 255)/256, 256>>>((const float4*)query, (uint2*)xqh, (uint2*)xql, B*S*D/4);
    split_f32<<<(B*S*D/4 + 255)/256, 256>>>((const float4*)value, (uint2*)xvh, (uint2*)xvl, B*S*D/4);
    split_f32<<<(D*D/4 + 255)/256, 256>>>((const float4*)Wq, (uint2*)wqh, (uint2*)wql, D*D/4);
    split_f32<<<(D*D/4 + 255)/256, 256>>>((const float4*)Wv, (uint2*)wvh, (uint2*)wvl, D*D/4);

    // 1) projections (bf16 3-term)
    dim3 gp(D / BN, (B * S) / BM, 1);
    gemm_nt<3,0,2><<<gp, THREADS, SMEM_DYN>>>(xqh, xql, wqh, wql,
                                              nullptr, Qh, Ql, D, D,
                                              bq, qkb, 1.0f, 0, 0, 0);
    gemm_nt<3,0,3><<<gp, THREADS, SMEM_DYN>>>(xvh, xvl, wvh, wvl,
                                              V, Vh, Vl, D, D,
                                              bv, nullptr, 1.0f, 0, 0, 0);

    // 2) Vt fp16 split
    transpose_split<<<dim3(S / 32, D / 32, B), dim3(32, 8)>>>(V, Vth, Vtl);

    // 3) scores: S[b] = Q[b]·V[b]^T / 8 (bf16 3-term, fp32 out)
    dim3 gs(S / BN, S / BM, B);
    gemm_nt<3,0,1><<<gs, THREADS, SMEM_DYN>>>(Qh, Ql, Vh, Vl,
                                              Sc, nullptr, nullptr, D, S,
                                              nullptr, nullptr, 0.125f, sd, sd, ss);

    // 4) softmax -> P fp16
    softmax_rows<<<B * S, 512>>>(Sc, Ph);

    // 5) out[b] = P[b]·Vt[b]^T (fp16 2-term, fp32 out)
    dim3 go(D / BN, S / BM, B);
    gemm_nt<2,1,1><<<go, THREADS, SMEM_DYN>>>(Ph, nullptr, Vth, Vtl,
                                              out, nullptr, nullptr, S, D,
                                              nullptr, nullptr, 1.0f, ss, sd, sd);
}

// round 9
// speedup vs baseline: 3.4689x; 1.0430x over previous
#include <cuda_runtime.h>
#include <cuda_bf16.h>
#include <cuda_fp16.h>
#include <cstdint>

#define BATCH  4
#define SEQ    4096
#define DMODEL 1024

// GEMM: CTA 128x256, 256 threads (8 warps as 2x4), warp tile 64x64.
// K in chunks of 32; pre-split 16-bit operands in gmem; 3-stage cp.async.
#define BM 128
#define BN 256
#define THREADS 256
#define ROW_B   80                    // 32 elems (64B) + 16B pad
#define A_HALF  (128 * ROW_B)         // 10240
#define B_HALF  (256 * ROW_B)         // 20480
#define OFF_AL  A_HALF                // 10240
#define OFF_BH  (2 * A_HALF)          // 20480
#define OFF_BL  (2 * A_HALF + B_HALF) // 40960
#define STAGE_B (2 * A_HALF + 2 * B_HALF)  // 61440
#define SMEM_DYN (3 * STAGE_B)        // 184320

// ---------------------------------------------------------------------------
// Scratch (device globals; allocation forbidden)
// ---------------------------------------------------------------------------
#define SD ((size_t)BATCH * SEQ * DMODEL)   // 16M
#define SS ((size_t)BATCH * SEQ * SEQ)      // 64M
__device__ uint16_t g_xqh[SD], g_xql[SD];            // split(query) bf16
__device__ uint16_t g_xvh[SD], g_xvl[SD];            // split(value) bf16
__device__ uint16_t g_wqh[DMODEL*DMODEL], g_wql[DMODEL*DMODEL];
__device__ uint16_t g_wvh[DMODEL*DMODEL], g_wvl[DMODEL*DMODEL];
__device__ uint16_t g_Qh[SD], g_Ql[SD];              // Q proj split bf16
__device__ float    g_V[SD];                         // V proj fp32
__device__ uint16_t g_Vh[SD], g_Vl[SD];              // V proj split bf16
__device__ uint16_t g_Vth[SD];                       // V^T fp16 (single)
__device__ float    g_S[SS];                         // scores fp32
__device__ uint16_t g_Ph[SS];                        // softmax(P) fp16

// ---------------------------------------------------------------------------
// helpers
// ---------------------------------------------------------------------------
__device__ __forceinline__ uint32_t smem_u32(const void* p) {
    uint32_t a;
    asm("{ .reg .u64 t; cvta.to.shared.u64 t, %1; cvt.u32.u64 %0, t; }" : "=r"(a) : "l"(p));
    return a;
}
__device__ __forceinline__ void cpasync16(uint32_t dst, const void* src) {
    asm volatile("{ .reg .u64 g; cvta.to.global.u64 g, %1; "
                 "cp.async.cg.shared.global [%0], [g], 16; }"
                 :: "r"(dst), "l"(src) : "memory");
}
#define CP_COMMIT() asm volatile("cp.async.commit_group;" ::: "memory")
#define CP_WAIT(n)  asm volatile("cp.async.wait_group %0;" :: "n"(n) : "memory")

#define LDSM4(d, addr) \
    asm volatile("ldmatrix.sync.aligned.m8n8.x4.shared.b16 {%0,%1,%2,%3}, [%4];" \
        : "=r"((d)[0]), "=r"((d)[1]), "=r"((d)[2]), "=r"((d)[3]) : "r"(addr))

template<int FP16>
__device__ __forceinline__ void mma16(float* d, const uint32_t* a,
                                      uint32_t b0, uint32_t b1v) {
    if constexpr (FP16) {
        asm volatile("mma.sync.aligned.m16n8k16.row.col.f32.f16.f16.f32 "
            "{%0,%1,%2,%3}, {%4,%5,%6,%7}, {%8,%9}, {%0,%1,%2,%3};"
            : "+f"(d[0]), "+f"(d[1]), "+f"(d[2]), "+f"(d[3])
            : "r"(a[0]), "r"(a[1]), "r"(a[2]), "r"(a[3]), "r"(b0), "r"(b1v));
    } else {
        asm volatile("mma.sync.aligned.m16n8k16.row.col.f32.bf16.bf16.f32 "
            "{%0,%1,%2,%3}, {%4,%5,%6,%7}, {%8,%9}, {%0,%1,%2,%3};"
            : "+f"(d[0]), "+f"(d[1]), "+f"(d[2]), "+f"(d[3])
            : "r"(a[0]), "r"(a[1]), "r"(a[2]), "r"(a[3]), "r"(b0), "r"(b1v));
    }
}

__device__ __forceinline__ void split2(float x, float y, uint32_t& hi, uint32_t& lo) {
    __nv_bfloat16 hx = __float2bfloat16(x), hy = __float2bfloat16(y);
    __nv_bfloat162 hp(hx, hy);
    hi = *reinterpret_cast<uint32_t*>(&hp);
    __nv_bfloat162 lp = __floats2bfloat162_rn(x - __bfloat162float(hx),
                                              y - __bfloat162float(hy));
    lo = *reinterpret_cast<uint32_t*>(&lp);
}

// ---------------------------------------------------------------------------
// 16-bit split NT GEMM:  C[m,n] = scale * sum_k A[m,k]*B[n,k] (+ b1 + b2)
// TERMS=3: Ah*Bh + Ah*Bl + Al*Bh   (bf16 3-term)
// TERMS=2: Ah*Bh + Ah*Bl           (A single / B split)
// TERMS=1: Ah*Bh                   (both single)
// MODE bit0: fp32 C ; bit1: bf16 split Ch/Cl
// ---------------------------------------------------------------------------
template<int TERMS, int FP16, int MODE>
__global__ __launch_bounds__(THREADS, 1)
void gemm_nt(const uint16_t* __restrict__ Ah, const uint16_t* __restrict__ Al,
             const uint16_t* __restrict__ Bh, const uint16_t* __restrict__ Bl,
             float* __restrict__ C, uint16_t* __restrict__ Ch, uint16_t* __restrict__ Cl,
             int K, int ldc,
             const float* __restrict__ b1, const float* __restrict__ b2,
             float scale,
             long long aB, long long bB, long long cB)
{
    extern __shared__ char smem[];
    const uint32_t sbase = smem_u32(smem);
    const int tid = threadIdx.x, lane = tid & 31, w = tid >> 5;
    const int wm = w & 1, wn = w >> 1;

    Ah += (long long)blockIdx.z * aB;
    if (TERMS == 3) Al += (long long)blockIdx.z * aB;
    Bh += (long long)blockIdx.z * bB;
    if (TERMS >= 2) Bl += (long long)blockIdx.z * bB;
    const long long cOff = (long long)blockIdx.z * cB;
    const int m0 = blockIdx.y * BM;
    const int n0 = blockIdx.x * BN;

    const uint32_t offA = (uint32_t)((wm * 64 + ((lane >> 3) & 1) * 8 + (lane & 7)) * ROW_B
                                     + ((lane >> 4) & 1) * 16);
    const uint32_t offB = (uint32_t)((wn * 64 + ((lane >> 4) & 1) * 8 + (lane & 7)) * ROW_B
                                     + ((lane >> 3) & 1) * 16);

    float acc[4][8][4];
    #pragma unroll
    for (int i = 0; i < 4; ++i)
        #pragma unroll
        for (int j = 0; j < 8; ++j)
            #pragma unroll
            for (int q = 0; q < 4; ++q) acc[i][j][q] = 0.f;

    const int nc = K >> 5;

    auto issue = [&](int c, int s) {
        const uint32_t sb = sbase + (uint32_t)s * STAGE_B;
        const int k0 = c * 32;
        #pragma unroll
        for (int i = 0; i < 2; ++i) {                 // A: 512 16B-chunks
            int idx = tid + i * 256;
            int row = idx >> 2, cc = idx & 3;
            const uint32_t d = sb + row * ROW_B + cc * 16;
            const long long g = (long long)(m0 + row) * K + k0 + cc * 8;
            cpasync16(d, Ah + g);
            if (TERMS == 3) cpasync16(d + OFF_AL, Al + g);
        }
        #pragma unroll
        for (int i = 0; i < 4; ++i) {                 // B: 1024 16B-chunks
            int idx = tid + i * 256;
            int row = idx >> 2, cc = idx & 3;
            const uint32_t d = sb + row * ROW_B + cc * 16;
            const long long g = (long long)(n0 + row) * K + k0 + cc * 8;
            cpasync16(d + OFF_BH, Bh + g);
            if (TERMS >= 2) cpasync16(d + OFF_BL, Bl + g);
        }
    };

    issue(0, 0); CP_COMMIT();
    issue(1, 1); CP_COMMIT();

    int st = 0;       // compute stage
    int si = 2;       // next issue stage
    for (int c = 0; c < nc; ++c) {
        if (c == nc - 1) { CP_WAIT(0); } else { CP_WAIT(1); }
        __syncthreads();

        // issue c+2 FIRST so the async engine runs under the MMAs below
        if (c + 2 < nc) { issue(c + 2, si); CP_COMMIT(); }

        const uint32_t base = sbase + (uint32_t)st * STAGE_B;
        #pragma unroll
        for (int kk2 = 0; kk2 < 2; ++kk2) {
            const uint32_t kb = kk2 * 32;
            uint32_t ah[4][4], bhf[4][4];
            #pragma unroll
            for (int mi = 0; mi < 4; ++mi) LDSM4(ah[mi], base + offA + mi * (16 * ROW_B) + kb);
            #pragma unroll
            for (int nt = 0; nt < 4; ++nt) LDSM4(bhf[nt], base + OFF_BH + offB + nt * (16 * ROW_B) + kb);
            // hi * hi
            #pragma unroll
            for (int mi = 0; mi < 4; ++mi)
                #pragma unroll
                for (int nt = 0; nt < 4; ++nt)
                    #pragma unroll
                    for (int nh = 0; nh < 2; ++nh)
                        mma16<FP16>(acc[mi][nt * 2 + nh], ah[mi], bhf[nt][nh * 2], bhf[nt][nh * 2 + 1]);
            // hi * lo
            if constexpr (TERMS >= 2) {
                uint32_t blf[4][4];
                #pragma unroll
                for (int nt = 0; nt < 4; ++nt) LDSM4(blf[nt], base + OFF_BL + offB + nt * (16 * ROW_B) + kb);
                #pragma unroll
                for (int mi = 0; mi < 4; ++mi)
                    #pragma unroll
                    for (int nt = 0; nt < 4; ++nt)
                        #pragma unroll
                        for (int nh = 0; nh < 2; ++nh)
                            mma16<FP16>(acc[mi][nt * 2 + nh], ah[mi], blf[nt][nh * 2], blf[nt][nh * 2 + 1]);
            }
            // lo * hi
            if constexpr (TERMS == 3) {
                uint32_t alf[4][4];
                #pragma unroll
                for (int mi = 0; mi < 4; ++mi) LDSM4(alf[mi], base + OFF_AL + offA + mi * (16 * ROW_B) + kb);
                #pragma unroll
                for (int mi = 0; mi < 4; ++mi)
                    #pragma unroll
                    for (int nt = 0; nt < 4; ++nt)
                        #pragma unroll
                        for (int nh = 0; nh < 2; ++nh)
                            mma16<FP16>(acc[mi][nt * 2 + nh], alf[mi], bhf[nt][nh * 2], bhf[nt][nh * 2 + 1]);
            }
        }

        if (++st == 3) st = 0;
        if (++si == 3) si = 0;
    }

    // epilogue
    const int gid = lane >> 2, tig = lane & 3;
    #pragma unroll
    for (int mi = 0; mi < 4; ++mi) {
        const int row = m0 + wm * 64 + mi * 16 + gid;
        #pragma unroll
        for (int ni = 0; ni < 8; ++ni) {
            const int col = n0 + wn * 64 + ni * 8 + tig * 2;
            float bb0 = 0.f, bb1 = 0.f;
            if (b1) { bb0 += b1[col]; bb1 += b1[col + 1]; }
            if (b2) { bb0 += b2[col]; bb1 += b2[col + 1]; }
            float2 o0, o1;
            o0.x = acc[mi][ni][0] * scale + bb0;
            o0.y = acc[mi][ni][1] * scale + bb1;
            o1.x = acc[mi][ni][2] * scale + bb0;
            o1.y = acc[mi][ni][3] * scale + bb1;
            const long long i0 = cOff + (long long)row * ldc + col;
            const long long i1 = i0 + 8LL * ldc;
            if constexpr (MODE & 1) {
                *(float2*)(C + i0) = o0;
                *(float2*)(C + i1) = o1;
            }
            if constexpr (MODE & 2) {
                uint32_t h, l;
                split2(o0.x, o0.y, h, l);
                *(uint32_t*)(Ch + i0) = h; *(uint32_t*)(Cl + i0) = l;
                split2(o1.x, o1.y, h, l);
                *(uint32_t*)(Ch + i1) = h; *(uint32_t*)(Cl + i1) = l;
            }
        }
    }
}

// ---------------------------------------------------------------------------
// split fp32 -> bf16 hi/lo (vectorized)
// ---------------------------------------------------------------------------
__global__ __launch_bounds__(256)
void split_f32(const float4* __restrict__ in, uint2* __restrict__ hi,
               uint2* __restrict__ lo, int n4)
{
    int i = blockIdx.x * 256 + threadIdx.x;
    if (i >= n4) return;
    float4 v = in[i];
    uint32_t h0, l0, h1, l1;
    split2(v.x, v.y, h0, l0);
    split2(v.z, v.w, h1, l1);
    hi[i] = make_uint2(h0, h1);
    lo[i] = make_uint2(l0, l1);
}

// ---------------------------------------------------------------------------
// V transpose -> fp16: Vth[b][d][s] = f16(V[b][s][d])
// ---------------------------------------------------------------------------
__global__ __launch_bounds__(256)
void transpose_v16(const float* __restrict__ V, uint16_t* __restrict__ Vth)
{
    __shared__ float t[32][33];
    const int b  = blockIdx.z;
    const int s0 = blockIdx.x * 32;
    const int d0 = blockIdx.y * 32;
    const float* Vb = V + (long long)b * SEQ * DMODEL;
    uint16_t* Hh = Vth + (long long)b * SEQ * DMODEL;
    const int x = threadIdx.x, y = threadIdx.y;   // 32 x 8
    #pragma unroll
    for (int i = 0; i < 32; i += 8)
        t[y + i][x] = Vb[(long long)(s0 + y + i) * DMODEL + d0 + x];
    __syncthreads();
    #pragma unroll
    for (int i = 0; i < 32; i += 8) {
        __half h = __float2half_rn(t[x][y + i]);
        Hh[(long long)(d0 + y + i) * SEQ + s0 + x] = *reinterpret_cast<uint16_t*>(&h);
    }
}

// ---------------------------------------------------------------------------
// Row softmax: fp32 S row in, fp16 P row out
// ---------------------------------------------------------------------------
__global__ __launch_bounds__(512)
void softmax_rows(const float* __restrict__ S, uint16_t* __restrict__ Ph)
{
    const float* p = S + (long long)blockIdx.x * SEQ;
    const int tid = threadIdx.x;

    float4 a = ((const float4*)p)[tid];
    float4 b = ((const float4*)p)[tid + 512];

    __shared__ float sred[16];
    __shared__ float sval;

    float m = fmaxf(fmaxf(fmaxf(a.x, a.y), fmaxf(a.z, a.w)),
                    fmaxf(fmaxf(b.x, b.y), fmaxf(b.z, b.w)));
    #pragma unroll
    for (int o = 16; o > 0; o >>= 1) m = fmaxf(m, __shfl_xor_sync(0xffffffffu, m, o));
    if ((tid & 31) == 0) sred[tid >> 5] = m;
    __syncthreads();
    if (tid < 32) {
        float x = (tid < 16) ? sred[tid] : __int_as_float(0xff800000);
        #pragma unroll
        for (int o = 8; o > 0; o >>= 1) x = fmaxf(x, __shfl_xor_sync(0xffffffffu, x, o));
        if (tid == 0) sval = x;
    }
    __syncthreads();
    const float rmax = sval;
    __syncthreads();

    a.x = expf(a.x - rmax); a.y = expf(a.y - rmax);
    a.z = expf(a.z - rmax); a.w = expf(a.w - rmax);
    b.x = expf(b.x - rmax); b.y = expf(b.y - rmax);
    b.z = expf(b.z - rmax); b.w = expf(b.w - rmax);

    float s = (a.x + a.y) + (a.z + a.w) + (b.x + b.y) + (b.z + b.w);
    #pragma unroll
    for (int o = 16; o > 0; o >>= 1) s += __shfl_xor_sync(0xffffffffu, s, o);
    if ((tid & 31) == 0) sred[tid >> 5] = s;
    __syncthreads();
    if (tid < 32) {
        float x = (tid < 16) ? sred[tid] : 0.f;
        #pragma unroll
        for (int o = 8; o > 0; o >>= 1) x += __shfl_xor_sync(0xffffffffu, x, o);
        if (tid == 0) sval = x;
    }
    __syncthreads();
    const float inv = 1.0f / sval;

    __half2 p0 = __floats2half2_rn(a.x * inv, a.y * inv);
    __half2 p1 = __floats2half2_rn(a.z * inv, a.w * inv);
    __half2 p2 = __floats2half2_rn(b.x * inv, b.y * inv);
    __half2 p3 = __floats2half2_rn(b.z * inv, b.w * inv);

    const long long rb = (long long)blockIdx.x * (SEQ / 4);
    ((uint2*)Ph)[rb + tid]       = make_uint2(*reinterpret_cast<uint32_t*>(&p0),
                                              *reinterpret_cast<uint32_t*>(&p1));
    ((uint2*)Ph)[rb + 512 + tid] = make_uint2(*reinterpret_cast<uint32_t*>(&p2),
                                              *reinterpret_cast<uint32_t*>(&p3));
}

// ---------------------------------------------------------------------------
// Launcher
// ---------------------------------------------------------------------------
extern "C" void kernel_launch(void* const* d_in, const int* in_sizes, int n_in,
                              void* d_out, int out_size)
{
    const float* query = (const float*)d_in[0];
    const float* value = (const float*)d_in[1];
    const float* Wq    = (const float*)d_in[2];
    const float* bq    = (const float*)d_in[3];
    const float* qkb   = (const float*)d_in[4];
    const float* Wv    = (const float*)d_in[5];
    const float* bv    = (const float*)d_in[6];
    float* out = (float*)d_out;

    uint16_t *xqh, *xql, *xvh, *xvl, *wqh, *wql, *wvh, *wvl;
    uint16_t *Qh, *Ql, *Vh, *Vl, *Vth, *Ph;
    float *V, *Sc;
    cudaGetSymbolAddress((void**)&xqh, g_xqh); cudaGetSymbolAddress((void**)&xql, g_xql);
    cudaGetSymbolAddress((void**)&xvh, g_xvh); cudaGetSymbolAddress((void**)&xvl, g_xvl);
    cudaGetSymbolAddress((void**)&wqh, g_wqh); cudaGetSymbolAddress((void**)&wql, g_wql);
    cudaGetSymbolAddress((void**)&wvh, g_wvh); cudaGetSymbolAddress((void**)&wvl, g_wvl);
    cudaGetSymbolAddress((void**)&Qh,  g_Qh);  cudaGetSymbolAddress((void**)&Ql,  g_Ql);
    cudaGetSymbolAddress((void**)&V,   g_V);
    cudaGetSymbolAddress((void**)&Vh,  g_Vh);  cudaGetSymbolAddress((void**)&Vl,  g_Vl);
    cudaGetSymbolAddress((void**)&Vth, g_Vth);
    cudaGetSymbolAddress((void**)&Sc,  g_S);
    cudaGetSymbolAddress((void**)&Ph,  g_Ph);

    static bool attr_done = false;
    if (!attr_done) {
        cudaFuncSetAttribute(gemm_nt<3,0,1>, cudaFuncAttributeMaxDynamicSharedMemorySize, SMEM_DYN);
        cudaFuncSetAttribute(gemm_nt<3,0,2>, cudaFuncAttributeMaxDynamicSharedMemorySize, SMEM_DYN);
        cudaFuncSetAttribute(gemm_nt<3,0,3>, cudaFuncAttributeMaxDynamicSharedMemorySize, SMEM_DYN);
        cudaFuncSetAttribute(gemm_nt<1,1,1>, cudaFuncAttributeMaxDynamicSharedMemorySize, SMEM_DYN);
        attr_done = true;
    }

    const int S = SEQ, D = DMODEL, B = BATCH;
    const long long sd = (long long)S * D;
    const long long ss = (long long)S * S;

    // 0) split raw inputs + weights to bf16 hi/lo
    split_f32<<<(B*S*D/4 + 255)/256, 256>>>((const float4*)query, (uint2*)xqh, (uint2*)xql, B*S*D/4);
    split_f32<<<(B*S*D/4 + 255)/256, 256>>>((const float4*)value, (uint2*)xvh, (uint2*)xvl, B*S*D/4);
    split_f32<<<(D*D/4 + 255)/256, 256>>>((const float4*)Wq, (uint2*)wqh, (uint2*)wql, D*D/4);
    split_f32<<<(D*D/4 + 255)/256, 256>>>((const float4*)Wv, (uint2*)wvh, (uint2*)wvl, D*D/4);

    // 1) projections (bf16 3-term)
    dim3 gp(D / BN, (B * S) / BM, 1);
    gemm_nt<3,0,2><<<gp, THREADS, SMEM_DYN>>>(xqh, xql, wqh, wql,
                                              nullptr, Qh, Ql, D, D,
                                              bq, qkb, 1.0f, 0, 0, 0);
    gemm_nt<3,0,3><<<gp, THREADS, SMEM_DYN>>>(xvh, xvl, wvh, wvl,
                                              V, Vh, Vl, D, D,
                                              bv, nullptr, 1.0f, 0, 0, 0);

    // 2) Vt fp16 (single precision term)
    transpose_v16<<<dim3(S / 32, D / 32, B), dim3(32, 8)>>>(V, Vth);

    // 3) scores: S[b] = Q[b]·V[b]^T / 8 (bf16 3-term, fp32 out)
    dim3 gs(S / BN, S / BM, B);
    gemm_nt<3,0,1><<<gs, THREADS, SMEM_DYN>>>(Qh, Ql, Vh, Vl,
                                              Sc, nullptr, nullptr, D, S,
                                              nullptr, nullptr, 0.125f, sd, sd, ss);

    // 4) softmax -> P fp16
    softmax_rows<<<B * S, 512>>>(Sc, Ph);

    // 5) out[b] = P[b]·Vt[b]^T (fp16 1-term, fp32 out)
    dim3 go(D / BN, S / BM, B);
    gemm_nt<1,1,1><<<go, THREADS, SMEM_DYN>>>(Ph, nullptr, Vth, nullptr,
                                              out, nullptr, nullptr, S, D,
                                              nullptr, nullptr, 1.0f, ss, sd, sd);
}